// round 11
// baseline (speedup 1.0000x reference)
#include <cuda_runtime.h>
#include <cuda_fp16.h>
#include <cstdint>
#include <cstddef>

// ============================================================================
//   out[t,m] = sum_j xr[t,j] * Wcat[m,j],  xr = [x@Pi1^T | x@Pi2^T]  (K = 8192)
//   xr[t,j]  = sum_k x[t,k]  * Pcat[j,k]   (Pcat = [Pi1; Pi2], N = 8192, K = 4096)
//   GEMM2 dequantizes W from packed 4-bit indices inside its tile loader.
// ============================================================================
#define TOK    512
#define NF     4096
#define KSTEP  64                          // halves of K per stage (128 B rows)
#define NSTG   3
#define TT     128
#define TJ     128
#define STAGE_ROWS (TT + TJ)               // 256
#define STAGE_BYTES (STAGE_ROWS * 128)     // 32768
#define SMEM_G1 (NSTG * STAGE_BYTES)       // 98304  -> 2 CTAs/SM
#define SMEM_G2 (NSTG * STAGE_BYTES + 2048)// + codebook-pair table

// ============================================================================
// Device scratch (no cudaMalloc allowed)
// ============================================================================
static __device__ __half g_x16[(size_t)TOK * NF];          //  4 MB
static __device__ __half g_P16[(size_t)2 * NF * NF];       // 64 MB  [Pi1; Pi2]
static __device__ __half g_xr [(size_t)TOK * 2 * NF];      //  8 MB  [xr1 | xr2]

static __device__ __forceinline__ uint32_t smem_u32(const void* p) {
    uint32_t a;
    asm("{ .reg .u64 t; cvta.to.shared.u64 t, %1; cvt.u32.u64 %0, t; }"
        : "=r"(a) : "l"(p));
    return a;
}

#define TQ_LDSM4(r0, r1, r2, r3, addr) \
    asm volatile("ldmatrix.sync.aligned.m8n8.x4.shared.b16 {%0,%1,%2,%3}, [%4];" \
                 : "=r"(r0), "=r"(r1), "=r"(r2), "=r"(r3) : "r"(addr))

// ============================================================================
// Prep kernel 1: Pi and Pi2 fp32 -> fp16 into g_P16 (one launch)
// grid = 2*NF*NF/4 / 1024 = 8192 blocks, no bounds check needed.
// ============================================================================
__global__ void tq_f2h_pp(const float4* __restrict__ Pi, const float4* __restrict__ Pi2,
                          __half2* __restrict__ out) {
    const int n4 = NF * NF / 4;
    int i = blockIdx.x * (blockDim.x * 4) + threadIdx.x;
    #pragma unroll
    for (int j = 0; j < 4; ++j) {
        int k = i + j * blockDim.x;
        float4 v = (k < n4) ? Pi[k] : Pi2[k - n4];
        out[2 * k]     = __floats2half2_rn(v.x, v.y);
        out[2 * k + 1] = __floats2half2_rn(v.z, v.w);
    }
}

// ============================================================================
// Prep kernel 2: x fp32 -> fp16, and zero the output buffer. 1024 blocks.
// ============================================================================
__global__ void tq_prep_x_zero(const float4* __restrict__ x, __half2* __restrict__ xo,
                               float4* __restrict__ zo) {
    int b = blockIdx.x;
    if (b < 512) {                       // 512 * 1024 f4 = TOK*NF/4
        int i = b * 1024 + threadIdx.x;
        #pragma unroll
        for (int j = 0; j < 4; ++j) {
            int k = i + j * 256;
            float4 v = x[k];
            xo[2 * k]     = __floats2half2_rn(v.x, v.y);
            xo[2 * k + 1] = __floats2half2_rn(v.z, v.w);
        }
    } else {                             // zero out: 512 * 1024 f4 = TOK*NF/4
        int i = (b - 512) * 1024 + threadIdx.x;
        #pragma unroll
        for (int j = 0; j < 4; ++j)
            zo[i + j * 256] = make_float4(0.f, 0.f, 0.f, 0.f);
    }
}

// ============================================================================
// GEMM1 (unchanged round-10 config): fp16 HMMA, fragment double-buffered.
//   xr[512, 8192] = x16 @ Pcat^T ; fp16 store.
// ============================================================================
__global__ void __launch_bounds__(256, 2)
tq_hgemm(const __half* __restrict__ X, int ldx,
         const __half* __restrict__ W, int ldw,
         int ksteps, __half* __restrict__ Ch, int ldc)
{
    extern __shared__ __align__(1024) char dsm[];
    const uint32_t smBase = smem_u32(dsm);

    const int tid = threadIdx.x;
    const int wid = tid >> 5;
    const int lid = tid & 31;
    const int wm  = wid >> 2;
    const int wn  = wid & 3;
    const int tBase = blockIdx.x * TT;
    const int jBase = blockIdx.y * TJ;

    const __half* xb = X + (size_t)tBase * ldx;
    const __half* wb = W + (size_t)jBase * ldw;

    auto load_stage = [&](int slot, int step) {
        const int k0 = step * KSTEP;
        #pragma unroll
        for (int s = 0; s < 8; ++s) {
            int q = tid + s * 256;
            int r = q >> 3;
            int c = q & 7;
            const __half* src = (r < TT ? xb + (size_t)r * ldx
                                        : wb + (size_t)(r - TT) * ldw) + k0 + c * 8;
            uint32_t dst = smBase + slot * STAGE_BYTES + r * 128 + ((c ^ (r & 7)) * 16);
            asm volatile("cp.async.cg.shared.global [%0], [%1], 16;"
                         :: "r"(dst), "l"(src));
        }
    };

    const int swz  = lid & 7;
    const int rowA = wm * 64 + (lid & 7) + ((lid >> 3) & 1) * 8;
    const int pA   = lid >> 4;
    const int rowB = TT + wn * 32 + (lid & 7) + ((lid >> 4) & 1) * 8;
    const int pB   = (lid >> 3) & 1;

    float acc[4][4][4];
    #pragma unroll
    for (int a = 0; a < 4; ++a)
        #pragma unroll
        for (int b = 0; b < 4; ++b)
            #pragma unroll
            for (int c = 0; c < 4; ++c) acc[a][b][c] = 0.f;

    load_stage(0, 0);
    asm volatile("cp.async.commit_group;" ::: "memory");
    load_stage(1, 1);
    asm volatile("cp.async.commit_group;" ::: "memory");

    uint32_t a[2][4][4];
    uint32_t b[2][4][2];

    auto ldfrag = [&](int buf, uint32_t sb, int kb) {
        #pragma unroll
        for (int mi = 0; mi < 4; ++mi) {
            uint32_t ad = sb + (uint32_t)(rowA + mi * 16) * 128
                        + (uint32_t)(((kb * 2 + pA) ^ swz) * 16);
            TQ_LDSM4(a[buf][mi][0], a[buf][mi][1], a[buf][mi][2], a[buf][mi][3], ad);
        }
        #pragma unroll
        for (int gi = 0; gi < 2; ++gi) {
            uint32_t bd = sb + (uint32_t)(rowB + gi * 16) * 128
                        + (uint32_t)(((kb * 2 + pB) ^ swz) * 16);
            TQ_LDSM4(b[buf][2 * gi][0], b[buf][2 * gi][1],
                     b[buf][2 * gi + 1][0], b[buf][2 * gi + 1][1], bd);
        }
    };

    auto domma = [&](int buf) {
        #pragma unroll
        for (int mi = 0; mi < 4; ++mi)
            #pragma unroll
            for (int ni = 0; ni < 4; ++ni) {
                asm volatile(
                    "mma.sync.aligned.m16n8k16.row.col.f32.f16.f16.f32 "
                    "{%0,%1,%2,%3}, {%4,%5,%6,%7}, {%8,%9}, {%0,%1,%2,%3};"
                    : "+f"(acc[mi][ni][0]), "+f"(acc[mi][ni][1]),
                      "+f"(acc[mi][ni][2]), "+f"(acc[mi][ni][3])
                    : "r"(a[buf][mi][0]), "r"(a[buf][mi][1]),
                      "r"(a[buf][mi][2]), "r"(a[buf][mi][3]),
                      "r"(b[buf][ni][0]), "r"(b[buf][ni][1]));
            }
    };

    int slot = 0, pfslot = 2;
    for (int it = 0; it < ksteps; ++it) {
        asm volatile("cp.async.wait_group 1;" ::: "memory");
        __syncthreads();

        const int pf = it + NSTG - 1;
        if (pf < ksteps) load_stage(pfslot, pf);
        asm volatile("cp.async.commit_group;" ::: "memory");

        const uint32_t sb = smBase + slot * STAGE_BYTES;
        if (++slot == NSTG) slot = 0;
        if (++pfslot == NSTG) pfslot = 0;

        ldfrag(0, sb, 0);
        #pragma unroll
        for (int kb = 0; kb < 4; ++kb) {
            const int cur = kb & 1;
            if (kb < 3) ldfrag(cur ^ 1, sb, kb + 1);
            domma(cur);
        }
    }

    const int g  = lid >> 2;
    const int tg = lid & 3;
    #pragma unroll
    for (int mi = 0; mi < 4; ++mi) {
        #pragma unroll
        for (int ni = 0; ni < 4; ++ni) {
            int row = tBase + wm * 64 + mi * 16 + g;
            int col = jBase + wn * 32 + ni * 8 + tg * 2;
            __half2 h0 = __floats2half2_rn(acc[mi][ni][0], acc[mi][ni][1]);
            __half2 h1 = __floats2half2_rn(acc[mi][ni][2], acc[mi][ni][3]);
            *reinterpret_cast<__half2*>(Ch + (size_t)row * ldc + col)       = h0;
            *reinterpret_cast<__half2*>(Ch + (size_t)(row + 8) * ldc + col) = h1;
        }
    }
}

// ============================================================================
// GEMM2 with fused in-loader dequant.
//   out[512, 4096] += xr @ Wcat^T, split-K 2 (z = pass index), atomicAdd.
//   W tile loader: packed 4-bit indices -> codebook-pair table (float2, fp32
//   math identical to the old dequant kernel) -> fp16 smem tile.
//   Register-prefetched one iteration ahead; single-buffered fragments.
// ============================================================================
__global__ void __launch_bounds__(256, 2)
tq_hgemm_dq(const __half* __restrict__ X, int ldx, int ksteps,
            const int* __restrict__ ip1, const float* __restrict__ nr1,
            const float* __restrict__ cb1,
            const int* __restrict__ ip2, const float* __restrict__ nr2,
            const float* __restrict__ cb2,
            float* __restrict__ Cf, int ldc)
{
    extern __shared__ __align__(1024) char dsm[];
    const uint32_t smBase = smem_u32(dsm);
    float2* tbl = reinterpret_cast<float2*>(dsm + NSTG * STAGE_BYTES);

    const int tid = threadIdx.x;
    const int wid = tid >> 5;
    const int lid = tid & 31;
    const int wm  = wid >> 2;
    const int wn  = wid & 3;
    const int tBase = blockIdx.x * TT;
    const int jBase = blockIdx.y * TJ;
    const int z     = blockIdx.z;
    const int kOff  = z * (ksteps * KSTEP);

    const int*   IP = z ? ip2 : ip1;
    const float* NR = z ? nr2 : nr1;
    const float* CB = z ? cb2 : cb1;

    // build codebook-pair table: tbl[b] = (cb[b&15], cb[b>>4])
    tbl[tid] = make_float2(CB[tid & 15], CB[(tid >> 4) & 15]);

    const __half* xb = X + (size_t)tBase * ldx + kOff;

    // ---- X loader (cp.async): 128 rows x 8 chunks = 1024, 4 per thread
    auto load_x = [&](int slot, int step) {
        const int k0 = step * KSTEP;
        #pragma unroll
        for (int s = 0; s < 4; ++s) {
            int q  = tid + s * 256;
            int rr = q >> 3;
            int c  = q & 7;
            const __half* src = xb + (size_t)rr * ldx + k0 + c * 8;
            uint32_t dst = smBase + slot * STAGE_BYTES + rr * 128 + ((c ^ (rr & 7)) * 16);
            asm volatile("cp.async.cg.shared.global [%0], [%1], 16;"
                         :: "r"(dst), "l"(src));
        }
    };

    // ---- W loader: thread t -> row r = t>>1, half h = t&1 (32 weights/step)
    const int r = tid >> 1;
    const int h = tid & 1;
    const int*   ipRow = IP + ((size_t)(jBase + r) << 11) + (h << 4);
    const float* nrRow = NR + ((jBase + r) << 5);

    int4 pk[4];
    float sc;
    auto load_w = [&](int step) {
        const int4* p4 = reinterpret_cast<const int4*>(ipRow + step * 32);
        pk[0] = p4[0]; pk[1] = p4[1]; pk[2] = p4[2]; pk[3] = p4[3];
        sc = __ldg(&nrRow[step >> 1]) * 0.08838834764831843f;   // 1/sqrt(128)
    };
    auto sts_w = [&](int slot) {
        const uint32_t base = smBase + slot * STAGE_BYTES + (TT + r) * 128;
        #pragma unroll
        for (int j = 0; j < 4; ++j) {
            int c = h * 4 + j;
            int4 p = pk[j];
            float2 f0 = tbl[p.x & 255], f1 = tbl[p.y & 255];
            float2 f2 = tbl[p.z & 255], f3 = tbl[p.w & 255];
            __half2 o0 = __floats2half2_rn(f0.x * sc, f0.y * sc);
            __half2 o1 = __floats2half2_rn(f1.x * sc, f1.y * sc);
            __half2 o2 = __floats2half2_rn(f2.x * sc, f2.y * sc);
            __half2 o3 = __floats2half2_rn(f3.x * sc, f3.y * sc);
            uint32_t dst = base + (uint32_t)(((c) ^ (r & 7)) * 16);
            asm volatile("st.shared.v4.b32 [%0], {%1,%2,%3,%4};"
                         :: "r"(dst),
                            "r"(*reinterpret_cast<uint32_t*>(&o0)),
                            "r"(*reinterpret_cast<uint32_t*>(&o1)),
                            "r"(*reinterpret_cast<uint32_t*>(&o2)),
                            "r"(*reinterpret_cast<uint32_t*>(&o3))
                         : "memory");
        }
    };

    const int swz  = lid & 7;
    const int rowA = wm * 64 + (lid & 7) + ((lid >> 3) & 1) * 8;
    const int pA   = lid >> 4;
    const int rowB = TT + wn * 32 + (lid & 7) + ((lid >> 4) & 1) * 8;
    const int pB   = (lid >> 3) & 1;

    float acc[4][4][4];
    #pragma unroll
    for (int a = 0; a < 4; ++a)
        #pragma unroll
        for (int b = 0; b < 4; ++b)
            #pragma unroll
            for (int c = 0; c < 4; ++c) acc[a][b][c] = 0.f;

    // ---- prologue
    load_x(0, 0);
    asm volatile("cp.async.commit_group;" ::: "memory");
    load_x(1, 1);
    asm volatile("cp.async.commit_group;" ::: "memory");
    __syncthreads();                 // table visible to all
    load_w(0); sts_w(0);
    load_w(1); sts_w(1);
    load_w(2);                       // prefetch for step 2

    for (int it = 0; it < ksteps; ++it) {
        asm volatile("cp.async.wait_group 1;" ::: "memory");
        __syncthreads();             // stage[it] fully ready (X + W)

        if (it + 2 < ksteps) {
            const int sW = (it + 2) % 3;
            sts_w(sW);               // store prefetched step it+2
            load_x(sW, it + 2);
            asm volatile("cp.async.commit_group;" ::: "memory");
            if (it + 3 < ksteps) load_w(it + 3);
        }

        const uint32_t sb = smBase + (it % 3) * STAGE_BYTES;

        #pragma unroll
        for (int kb = 0; kb < 4; ++kb) {
            uint32_t a[4][4];
            #pragma unroll
            for (int mi = 0; mi < 4; ++mi) {
                uint32_t ad = sb + (uint32_t)(rowA + mi * 16) * 128
                            + (uint32_t)(((kb * 2 + pA) ^ swz) * 16);
                TQ_LDSM4(a[mi][0], a[mi][1], a[mi][2], a[mi][3], ad);
            }
            uint32_t b[4][2];
            #pragma unroll
            for (int gi = 0; gi < 2; ++gi) {
                uint32_t bd = sb + (uint32_t)(rowB + gi * 16) * 128
                            + (uint32_t)(((kb * 2 + pB) ^ swz) * 16);
                TQ_LDSM4(b[2 * gi][0], b[2 * gi][1], b[2 * gi + 1][0], b[2 * gi + 1][1], bd);
            }
            #pragma unroll
            for (int mi = 0; mi < 4; ++mi)
                #pragma unroll
                for (int ni = 0; ni < 4; ++ni) {
                    asm volatile(
                        "mma.sync.aligned.m16n8k16.row.col.f32.f16.f16.f32 "
                        "{%0,%1,%2,%3}, {%4,%5,%6,%7}, {%8,%9}, {%0,%1,%2,%3};"
                        : "+f"(acc[mi][ni][0]), "+f"(acc[mi][ni][1]),
                          "+f"(acc[mi][ni][2]), "+f"(acc[mi][ni][3])
                        : "r"(a[mi][0]), "r"(a[mi][1]), "r"(a[mi][2]), "r"(a[mi][3]),
                          "r"(b[ni][0]), "r"(b[ni][1]));
                }
        }
    }

    // ---- epilogue: atomicAdd (split-K 2, order-independent sum)
    const int g  = lid >> 2;
    const int tg = lid & 3;
    #pragma unroll
    for (int mi = 0; mi < 4; ++mi) {
        #pragma unroll
        for (int ni = 0; ni < 4; ++ni) {
            int row = tBase + wm * 64 + mi * 16 + g;
            int col = jBase + wn * 32 + ni * 8 + tg * 2;
            atomicAdd(Cf + (size_t)row * ldc + col,           acc[mi][ni][0]);
            atomicAdd(Cf + (size_t)row * ldc + col + 1,       acc[mi][ni][1]);
            atomicAdd(Cf + (size_t)(row + 8) * ldc + col,     acc[mi][ni][2]);
            atomicAdd(Cf + (size_t)(row + 8) * ldc + col + 1, acc[mi][ni][3]);
        }
    }
}

// ============================================================================
// Launch: 4 launches; #4 (= ncu capture) is the fused GEMM2.
// ============================================================================
extern "C" void kernel_launch(void* const* d_in, const int* in_sizes, int n_in,
                              void* d_out, int out_size) {
    (void)in_sizes; (void)n_in; (void)out_size;
    const float* x    = (const float*)d_in[0];
    const float* Pi   = (const float*)d_in[1];
    const int*   idx1 = (const int*)  d_in[2];
    const float* nrm1 = (const float*)d_in[3];
    const float* cb1  = (const float*)d_in[4];
    const int*   idx2 = (const int*)  d_in[5];
    const float* nrm2 = (const float*)d_in[6];
    const float* cb2  = (const float*)d_in[7];
    const float* Pi2  = (const float*)d_in[8];
    float* out = (float*)d_out;

    __half *px16, *pP16, *pxr;
    cudaGetSymbolAddress((void**)&px16, g_x16);
    cudaGetSymbolAddress((void**)&pP16, g_P16);
    cudaGetSymbolAddress((void**)&pxr,  g_xr);

    cudaFuncSetAttribute(tq_hgemm,    cudaFuncAttributeMaxDynamicSharedMemorySize, SMEM_G1);
    cudaFuncSetAttribute(tq_hgemm_dq, cudaFuncAttributeMaxDynamicSharedMemorySize, SMEM_G2);

    // launch 1: Pi + Pi2 -> fp16
    tq_f2h_pp<<<8192, 256>>>((const float4*)Pi, (const float4*)Pi2, (__half2*)pP16);

    // launch 2: x -> fp16, zero out
    tq_prep_x_zero<<<1024, 256>>>((const float4*)x, (__half2*)px16, (float4*)out);

    // launch 3: GEMM1  xr[512, 8192] = x16 @ Pcat^T  (K = 4096)
    {
        dim3 grid(TOK / TT, 2 * NF / TJ, 1);   // (4, 64) = 256 CTAs
        tq_hgemm<<<grid, 256, SMEM_G1>>>(px16, NF, pP16, NF, NF / KSTEP, pxr, 2 * NF);
    }

    // launch 4 (ncu capture): GEMM2  out += xr @ Wcat^T  (split-K 2, fused dequant)
    {
        dim3 grid(TOK / TT, NF / TJ, 2);       // (4, 32, 2) = 256 CTAs
        tq_hgemm_dq<<<grid, 256, SMEM_G2>>>(pxr, 2 * NF, NF / KSTEP,
                                            idx1, nrm1, cb1, idx2, nrm2, cb2,
                                            out, NF);
    }
}

// round 12
// speedup vs baseline: 1.3153x; 1.3153x over previous
#include <cuda_runtime.h>
#include <cuda_fp16.h>
#include <cstdint>
#include <cstddef>

// ============================================================================
//   out[t,m] = sum_j xr[t,j] * Wcat[m,j],  xr = [x@Pi1^T | x@Pi2^T]  (K = 8192)
//   xr[t,j]  = sum_k x[t,k]  * Pcat[j,k]   (Pcat = [Pi1; Pi2], N = 8192, K = 4096)
// ============================================================================
#define TOK    512
#define NF     4096
#define KSTEP  64                          // halves of K per stage (128 B rows)
#define NSTG   3
#define TT     128
#define TJ     128
#define STAGE_ROWS (TT + TJ)               // 256
#define STAGE_BYTES (STAGE_ROWS * 128)     // 32768
#define SMEM_BYTES  (NSTG * STAGE_BYTES)   // 98304 -> 2 CTAs/SM
#define AUX_Y   10                         // 40 aux CTAs inside GEMM1 launch

// ============================================================================
// Device scratch (no cudaMalloc allowed)
// ============================================================================
static __device__ __half g_x16[(size_t)TOK * NF];          //  4 MB
static __device__ __half g_P16[(size_t)2 * NF * NF];       // 64 MB  [Pi1; Pi2]
static __device__ __half g_W16[(size_t)NF * 2 * NF];       // 64 MB  [W1 | W2] per row
static __device__ __half g_xr [(size_t)TOK * 2 * NF];      //  8 MB  [xr1 | xr2]

static __device__ __forceinline__ uint32_t smem_u32(const void* p) {
    uint32_t a;
    asm("{ .reg .u64 t; cvta.to.shared.u64 t, %1; cvt.u32.u64 %0, t; }"
        : "=r"(a) : "l"(p));
    return a;
}

#define TQ_LDSM4(r0, r1, r2, r3, addr) \
    asm volatile("ldmatrix.sync.aligned.m8n8.x4.shared.b16 {%0,%1,%2,%3}, [%4];" \
                 : "=r"(r0), "=r"(r1), "=r"(r2), "=r"(r3) : "r"(addr))

// ============================================================================
// Prep: x fp32 -> fp16 (512 blocks x 256 threads x 4 float4)
// ============================================================================
__global__ void tq_prep_x(const float4* __restrict__ x, __half2* __restrict__ xo) {
    int i = blockIdx.x * 1024 + threadIdx.x;
    #pragma unroll
    for (int j = 0; j < 4; ++j) {
        int k = i + j * 256;
        float4 v = x[k];
        xo[2 * k]     = __floats2half2_rn(v.x, v.y);
        xo[2 * k + 1] = __floats2half2_rn(v.z, v.w);
    }
}

// ============================================================================
// Prep: Pi and Pi2 fp32 -> fp16 into g_P16 (one launch, 8192 blocks)
// ============================================================================
__global__ void tq_f2h_pp(const float4* __restrict__ Pi, const float4* __restrict__ Pi2,
                          __half2* __restrict__ out) {
    const int n4 = NF * NF / 4;
    int i = blockIdx.x * (blockDim.x * 4) + threadIdx.x;
    #pragma unroll
    for (int j = 0; j < 4; ++j) {
        int k = i + j * blockDim.x;
        float4 v = (k < n4) ? Pi[k] : Pi2[k - n4];
        out[2 * k]     = __floats2half2_rn(v.x, v.y);
        out[2 * k + 1] = __floats2half2_rn(v.z, v.w);
    }
}

// ============================================================================
// Standalone dequant (pass 2): 4-bit unpack + codebook + norm -> fp16 @ koff.
// MLP 2 (measured 12.2 us).
// ============================================================================
__global__ void tq_dequant(const int4* __restrict__ IP4, const float* __restrict__ NRM,
                           const float* __restrict__ CB, __half* __restrict__ O, int koff) {
    __shared__ float cb[16];
    if (threadIdx.x < 16) cb[threadIdx.x] = CB[threadIdx.x];
    __syncthreads();
    int base = blockIdx.x * 512 + threadIdx.x;
    #pragma unroll
    for (int u = 0; u < 2; ++u) {
        int i = base + u * 256;
        if (i >= NF * (NF / 2) / 4) return;
        int m  = i >> 9;
        int c4 = i & 511;
        int4 p = IP4[i];
        float s = __ldg(&NRM[(m << 5) + (c4 >> 4)]) * 0.08838834764831843f;
        __half2 h[4];
        h[0] = __floats2half2_rn(cb[p.x & 15] * s, cb[(p.x >> 4) & 15] * s);
        h[1] = __floats2half2_rn(cb[p.y & 15] * s, cb[(p.y >> 4) & 15] * s);
        h[2] = __floats2half2_rn(cb[p.z & 15] * s, cb[(p.z >> 4) & 15] * s);
        h[3] = __floats2half2_rn(cb[p.w & 15] * s, cb[(p.w >> 4) & 15] * s);
        *reinterpret_cast<uint4*>(O + (size_t)m * (2 * NF) + koff + c4 * 8) =
            *reinterpret_cast<uint4*>(h);
    }
}

// ============================================================================
// GEMM1 + aux: tile 128x128, 8 warps, warp 64x32, 3-stage cp.async,
//   fragment double-buffered (r10 exact path, 95.0 us measured).
//   Aux CTAs (blockIdx.y >= jTiles): dq pass 1 (MLP 4, r8-proven) + zero out.
// ============================================================================
__global__ void __launch_bounds__(256, 2)
tq_hgemm_aux(const __half* __restrict__ X, int ldx,
             const __half* __restrict__ W, int ldw,
             int ksteps, int jTiles, __half* __restrict__ Ch, int ldc,
             const int4* __restrict__ dq_i1, const float* __restrict__ dq_n1,
             const float* __restrict__ dq_c1,
             __half* __restrict__ dq_out, float4* __restrict__ zero_out)
{
    extern __shared__ __align__(1024) char dsm[];

    // ---------------- aux path: dq1 + zero (72 MB total over 40 CTAs) -------
    if ((int)blockIdx.y >= jTiles) {
        float* cb = reinterpret_cast<float*>(dsm);   // 16 floats
        if (threadIdx.x < 16) cb[threadIdx.x] = dq_c1[threadIdx.x];
        __syncthreads();
        const int auxId  = (blockIdx.y - jTiles) * gridDim.x + blockIdx.x;
        const int nAux   = AUX_Y * gridDim.x;        // 40
        // zero the output (atomicAdd target of GEMM2), 4x float4 per iter
        {
            const int n4 = TOK * NF / 4;
            const int st = (auxId * 256 + threadIdx.x) * 4;
            const int sd = nAux * 256 * 4;
            for (int i = st; i < n4; i += sd) {
                #pragma unroll
                for (int u = 0; u < 4; ++u)
                    zero_out[i + u] = make_float4(0.f, 0.f, 0.f, 0.f);
            }
        }
        // dequant pass 1, MLP 4 (16 prefetch regs -> no spills)
        const int total   = NF * (NF / 2) / 4;
        const int start4  = (auxId * 256 + threadIdx.x) * 4;
        const int stride4 = nAux * 256 * 4;
        for (int i0 = start4; i0 < total; i0 += stride4) {
            int4 p[4];
            #pragma unroll
            for (int u = 0; u < 4; ++u) p[u] = dq_i1[i0 + u];
            #pragma unroll
            for (int u = 0; u < 4; ++u) {
                int i  = i0 + u;
                int m  = i >> 9;
                int c4 = i & 511;
                float s = __ldg(&dq_n1[(m << 5) + (c4 >> 4)]) * 0.08838834764831843f;
                __half2 h[4];
                h[0] = __floats2half2_rn(cb[p[u].x & 15] * s, cb[(p[u].x >> 4) & 15] * s);
                h[1] = __floats2half2_rn(cb[p[u].y & 15] * s, cb[(p[u].y >> 4) & 15] * s);
                h[2] = __floats2half2_rn(cb[p[u].z & 15] * s, cb[(p[u].z >> 4) & 15] * s);
                h[3] = __floats2half2_rn(cb[p[u].w & 15] * s, cb[(p[u].w >> 4) & 15] * s);
                *reinterpret_cast<uint4*>(dq_out + (size_t)m * (2 * NF) + c4 * 8) =
                    *reinterpret_cast<uint4*>(h);
            }
        }
        return;
    }

    // ---------------- GEMM path (r10 exact) --------------------------------
    const uint32_t smBase = smem_u32(dsm);
    const int tid = threadIdx.x;
    const int wid = tid >> 5;
    const int lid = tid & 31;
    const int wm  = wid >> 2;
    const int wn  = wid & 3;
    const int tBase = blockIdx.x * TT;
    const int jBase = blockIdx.y * TJ;

    const __half* xb = X + (size_t)tBase * ldx;
    const __half* wb = W + (size_t)jBase * ldw;

    auto load_stage = [&](int slot, int step) {
        const int k0 = step * KSTEP;
        #pragma unroll
        for (int s = 0; s < 8; ++s) {
            int q = tid + s * 256;
            int r = q >> 3;
            int c = q & 7;
            const __half* src = (r < TT ? xb + (size_t)r * ldx
                                        : wb + (size_t)(r - TT) * ldw) + k0 + c * 8;
            uint32_t dst = smBase + slot * STAGE_BYTES + r * 128 + ((c ^ (r & 7)) * 16);
            asm volatile("cp.async.cg.shared.global [%0], [%1], 16;"
                         :: "r"(dst), "l"(src));
        }
    };

    const int swz  = lid & 7;
    const int rowA = wm * 64 + (lid & 7) + ((lid >> 3) & 1) * 8;
    const int pA   = lid >> 4;
    const int rowB = TT + wn * 32 + (lid & 7) + ((lid >> 4) & 1) * 8;
    const int pB   = (lid >> 3) & 1;

    float acc[4][4][4];
    #pragma unroll
    for (int a = 0; a < 4; ++a)
        #pragma unroll
        for (int b = 0; b < 4; ++b)
            #pragma unroll
            for (int c = 0; c < 4; ++c) acc[a][b][c] = 0.f;

    load_stage(0, 0);
    asm volatile("cp.async.commit_group;" ::: "memory");
    load_stage(1, 1);
    asm volatile("cp.async.commit_group;" ::: "memory");

    uint32_t a[2][4][4];
    uint32_t b[2][4][2];

    auto ldfrag = [&](int buf, uint32_t sb, int kb) {
        #pragma unroll
        for (int mi = 0; mi < 4; ++mi) {
            uint32_t ad = sb + (uint32_t)(rowA + mi * 16) * 128
                        + (uint32_t)(((kb * 2 + pA) ^ swz) * 16);
            TQ_LDSM4(a[buf][mi][0], a[buf][mi][1], a[buf][mi][2], a[buf][mi][3], ad);
        }
        #pragma unroll
        for (int gi = 0; gi < 2; ++gi) {
            uint32_t bd = sb + (uint32_t)(rowB + gi * 16) * 128
                        + (uint32_t)(((kb * 2 + pB) ^ swz) * 16);
            TQ_LDSM4(b[buf][2 * gi][0], b[buf][2 * gi][1],
                     b[buf][2 * gi + 1][0], b[buf][2 * gi + 1][1], bd);
        }
    };

    auto domma = [&](int buf) {
        #pragma unroll
        for (int mi = 0; mi < 4; ++mi)
            #pragma unroll
            for (int ni = 0; ni < 4; ++ni) {
                asm volatile(
                    "mma.sync.aligned.m16n8k16.row.col.f32.f16.f16.f32 "
                    "{%0,%1,%2,%3}, {%4,%5,%6,%7}, {%8,%9}, {%0,%1,%2,%3};"
                    : "+f"(acc[mi][ni][0]), "+f"(acc[mi][ni][1]),
                      "+f"(acc[mi][ni][2]), "+f"(acc[mi][ni][3])
                    : "r"(a[buf][mi][0]), "r"(a[buf][mi][1]),
                      "r"(a[buf][mi][2]), "r"(a[buf][mi][3]),
                      "r"(b[buf][ni][0]), "r"(b[buf][ni][1]));
            }
    };

    int slot = 0, pfslot = 2;
    for (int it = 0; it < ksteps; ++it) {
        asm volatile("cp.async.wait_group 1;" ::: "memory");
        __syncthreads();

        const int pf = it + NSTG - 1;
        if (pf < ksteps) load_stage(pfslot, pf);
        asm volatile("cp.async.commit_group;" ::: "memory");

        const uint32_t sb = smBase + slot * STAGE_BYTES;
        if (++slot == NSTG) slot = 0;
        if (++pfslot == NSTG) pfslot = 0;

        ldfrag(0, sb, 0);
        #pragma unroll
        for (int kb = 0; kb < 4; ++kb) {
            const int cur = kb & 1;
            if (kb < 3) ldfrag(cur ^ 1, sb, kb + 1);
            domma(cur);
        }
    }

    const int g  = lid >> 2;
    const int tg = lid & 3;
    #pragma unroll
    for (int mi = 0; mi < 4; ++mi) {
        #pragma unroll
        for (int ni = 0; ni < 4; ++ni) {
            int row = tBase + wm * 64 + mi * 16 + g;
            int col = jBase + wn * 32 + ni * 8 + tg * 2;
            __half2 h0 = __floats2half2_rn(acc[mi][ni][0], acc[mi][ni][1]);
            __half2 h1 = __floats2half2_rn(acc[mi][ni][2], acc[mi][ni][3]);
            *reinterpret_cast<__half2*>(Ch + (size_t)row * ldc + col)       = h0;
            *reinterpret_cast<__half2*>(Ch + (size_t)(row + 8) * ldc + col) = h1;
        }
    }
}

// ============================================================================
// GEMM2 (r10 exact): split-K 2, fp32 atomicAdd epilogue.
// ============================================================================
__global__ void __launch_bounds__(256, 2)
tq_hgemm2(const __half* __restrict__ X, int ldx,
          const __half* __restrict__ W, int ldw,
          int ksteps, float* __restrict__ Cf, int ldc)
{
    extern __shared__ __align__(1024) char dsm[];
    const uint32_t smBase = smem_u32(dsm);

    const int tid = threadIdx.x;
    const int wid = tid >> 5;
    const int lid = tid & 31;
    const int wm  = wid >> 2;
    const int wn  = wid & 3;
    const int tBase = blockIdx.x * TT;
    const int jBase = blockIdx.y * TJ;
    const int kOff  = blockIdx.z * (ksteps * KSTEP);

    const __half* xb = X + (size_t)tBase * ldx + kOff;
    const __half* wb = W + (size_t)jBase * ldw + kOff;

    auto load_stage = [&](int slot, int step) {
        const int k0 = step * KSTEP;
        #pragma unroll
        for (int s = 0; s < 8; ++s) {
            int q = tid + s * 256;
            int r = q >> 3;
            int c = q & 7;
            const __half* src = (r < TT ? xb + (size_t)r * ldx
                                        : wb + (size_t)(r - TT) * ldw) + k0 + c * 8;
            uint32_t dst = smBase + slot * STAGE_BYTES + r * 128 + ((c ^ (r & 7)) * 16);
            asm volatile("cp.async.cg.shared.global [%0], [%1], 16;"
                         :: "r"(dst), "l"(src));
        }
    };

    const int swz  = lid & 7;
    const int rowA = wm * 64 + (lid & 7) + ((lid >> 3) & 1) * 8;
    const int pA   = lid >> 4;
    const int rowB = TT + wn * 32 + (lid & 7) + ((lid >> 4) & 1) * 8;
    const int pB   = (lid >> 3) & 1;

    float acc[4][4][4];
    #pragma unroll
    for (int a = 0; a < 4; ++a)
        #pragma unroll
        for (int b = 0; b < 4; ++b)
            #pragma unroll
            for (int c = 0; c < 4; ++c) acc[a][b][c] = 0.f;

    load_stage(0, 0);
    asm volatile("cp.async.commit_group;" ::: "memory");
    load_stage(1, 1);
    asm volatile("cp.async.commit_group;" ::: "memory");

    uint32_t a[2][4][4];
    uint32_t b[2][4][2];

    auto ldfrag = [&](int buf, uint32_t sb, int kb) {
        #pragma unroll
        for (int mi = 0; mi < 4; ++mi) {
            uint32_t ad = sb + (uint32_t)(rowA + mi * 16) * 128
                        + (uint32_t)(((kb * 2 + pA) ^ swz) * 16);
            TQ_LDSM4(a[buf][mi][0], a[buf][mi][1], a[buf][mi][2], a[buf][mi][3], ad);
        }
        #pragma unroll
        for (int gi = 0; gi < 2; ++gi) {
            uint32_t bd = sb + (uint32_t)(rowB + gi * 16) * 128
                        + (uint32_t)(((kb * 2 + pB) ^ swz) * 16);
            TQ_LDSM4(b[buf][2 * gi][0], b[buf][2 * gi][1],
                     b[buf][2 * gi + 1][0], b[buf][2 * gi + 1][1], bd);
        }
    };

    auto domma = [&](int buf) {
        #pragma unroll
        for (int mi = 0; mi < 4; ++mi)
            #pragma unroll
            for (int ni = 0; ni < 4; ++ni) {
                asm volatile(
                    "mma.sync.aligned.m16n8k16.row.col.f32.f16.f16.f32 "
                    "{%0,%1,%2,%3}, {%4,%5,%6,%7}, {%8,%9}, {%0,%1,%2,%3};"
                    : "+f"(acc[mi][ni][0]), "+f"(acc[mi][ni][1]),
                      "+f"(acc[mi][ni][2]), "+f"(acc[mi][ni][3])
                    : "r"(a[buf][mi][0]), "r"(a[buf][mi][1]),
                      "r"(a[buf][mi][2]), "r"(a[buf][mi][3]),
                      "r"(b[buf][ni][0]), "r"(b[buf][ni][1]));
            }
    };

    int slot = 0, pfslot = 2;
    for (int it = 0; it < ksteps; ++it) {
        asm volatile("cp.async.wait_group 1;" ::: "memory");
        __syncthreads();

        const int pf = it + NSTG - 1;
        if (pf < ksteps) load_stage(pfslot, pf);
        asm volatile("cp.async.commit_group;" ::: "memory");

        const uint32_t sb = smBase + slot * STAGE_BYTES;
        if (++slot == NSTG) slot = 0;
        if (++pfslot == NSTG) pfslot = 0;

        ldfrag(0, sb, 0);
        #pragma unroll
        for (int kb = 0; kb < 4; ++kb) {
            const int cur = kb & 1;
            if (kb < 3) ldfrag(cur ^ 1, sb, kb + 1);
            domma(cur);
        }
    }

    const int g  = lid >> 2;
    const int tg = lid & 3;
    #pragma unroll
    for (int mi = 0; mi < 4; ++mi) {
        #pragma unroll
        for (int ni = 0; ni < 4; ++ni) {
            int row = tBase + wm * 64 + mi * 16 + g;
            int col = jBase + wn * 32 + ni * 8 + tg * 2;
            atomicAdd(Cf + (size_t)row * ldc + col,           acc[mi][ni][0]);
            atomicAdd(Cf + (size_t)row * ldc + col + 1,       acc[mi][ni][1]);
            atomicAdd(Cf + (size_t)(row + 8) * ldc + col,     acc[mi][ni][2]);
            atomicAdd(Cf + (size_t)(row + 8) * ldc + col + 1, acc[mi][ni][3]);
        }
    }
}

// ============================================================================
// Launch: dq2, prep_x, f2h_pp, GEMM1+aux (ncu capture @ #4), GEMM2.
// ============================================================================
extern "C" void kernel_launch(void* const* d_in, const int* in_sizes, int n_in,
                              void* d_out, int out_size) {
    (void)in_sizes; (void)n_in; (void)out_size;
    const float* x    = (const float*)d_in[0];
    const float* Pi   = (const float*)d_in[1];
    const int*   idx1 = (const int*)  d_in[2];
    const float* nrm1 = (const float*)d_in[3];
    const float* cb1  = (const float*)d_in[4];
    const int*   idx2 = (const int*)  d_in[5];
    const float* nrm2 = (const float*)d_in[6];
    const float* cb2  = (const float*)d_in[7];
    const float* Pi2  = (const float*)d_in[8];
    float* out = (float*)d_out;

    __half *px16, *pP16, *pW16, *pxr;
    cudaGetSymbolAddress((void**)&px16, g_x16);
    cudaGetSymbolAddress((void**)&pP16, g_P16);
    cudaGetSymbolAddress((void**)&pW16, g_W16);
    cudaGetSymbolAddress((void**)&pxr,  g_xr);

    cudaFuncSetAttribute(tq_hgemm_aux, cudaFuncAttributeMaxDynamicSharedMemorySize,
                         SMEM_BYTES);
    cudaFuncSetAttribute(tq_hgemm2,    cudaFuncAttributeMaxDynamicSharedMemorySize,
                         SMEM_BYTES);

    const int ndq4 = NF * (NF / 2) / 4;

    // launch 1: dequant pass 2 (no dependencies; frees GEMM1's aux budget)
    tq_dequant<<<(ndq4 + 511) / 512, 256>>>((const int4*)idx2, nrm2, cb2, pW16, NF);

    // launch 2: x -> fp16
    tq_prep_x<<<512, 256>>>((const float4*)x, (__half2*)px16);

    // launch 3: Pi + Pi2 -> fp16
    tq_f2h_pp<<<8192, 256>>>((const float4*)Pi, (const float4*)Pi2, (__half2*)pP16);

    // launch 4 (ncu capture): GEMM1 (256 CTAs) + 40 aux CTAs (dq1 + zero)
    //   xr[512, 8192] = x16 @ Pcat^T  (K = 4096)
    {
        dim3 grid(TOK / TT, 2 * NF / TJ + AUX_Y, 1);   // (4, 74) = 296 CTAs
        tq_hgemm_aux<<<grid, 256, SMEM_BYTES>>>(
            px16, NF, pP16, NF, NF / KSTEP, 2 * NF / TJ, pxr, 2 * NF,
            (const int4*)idx1, nrm1, cb1, pW16, (float4*)out);
    }

    // launch 5: GEMM2  out += xr @ Wcat^T  (K = 8192, split-K 2)
    {
        dim3 grid(TOK / TT, NF / TJ, 2);               // (4, 32, 2) = 256 CTAs
        tq_hgemm2<<<grid, 256, SMEM_BYTES>>>(pxr, 2 * NF, pW16, 2 * NF,
                                             (2 * NF / KSTEP) / 2, out, NF);
    }
}

// round 13
// speedup vs baseline: 1.3838x; 1.0520x over previous
#include <cuda_runtime.h>
#include <cuda_fp16.h>
#include <cstdint>
#include <cstddef>

// ============================================================================
//   out[t,m] = sum_j xr[t,j] * Wcat[m,j],  xr = [x@Pi1^T | x@Pi2^T]  (K = 8192)
//   xr[t,j]  = sum_k x[t,k]  * Pcat[j,k]   (Pcat = [Pi1; Pi2], N = 8192, K = 4096)
// ============================================================================
#define TOK    512
#define NF     4096
#define KSTEP  64                          // halves of K per stage (128 B rows)
#define NSTG   3
#define TT     128
#define TJ     128
#define STAGE_ROWS (TT + TJ)               // 256
#define STAGE_BYTES (STAGE_ROWS * 128)     // 32768
#define SMEM_BYTES  (NSTG * STAGE_BYTES)   // 98304 -> 2 CTAs/SM
#define AUX_Y   10                         // 40 aux CTAs inside GEMM1 launch

// ============================================================================
// Device scratch (no cudaMalloc allowed)
// ============================================================================
static __device__ __half g_x16[(size_t)TOK * NF];          //  4 MB
static __device__ __half g_P16[(size_t)2 * NF * NF];       // 64 MB  [Pi1; Pi2]
static __device__ __half g_W16[(size_t)NF * 2 * NF];       // 64 MB  [W1 | W2] per row
static __device__ __half g_xr [(size_t)TOK * 2 * NF];      //  8 MB  [xr1 | xr2]

static __device__ __forceinline__ uint32_t smem_u32(const void* p) {
    uint32_t a;
    asm("{ .reg .u64 t; cvta.to.shared.u64 t, %1; cvt.u32.u64 %0, t; }"
        : "=r"(a) : "l"(p));
    return a;
}

#define TQ_LDSM4(r0, r1, r2, r3, addr) \
    asm volatile("ldmatrix.sync.aligned.m8n8.x4.shared.b16 {%0,%1,%2,%3}, [%4];" \
                 : "=r"(r0), "=r"(r1), "=r"(r2), "=r"(r3) : "r"(addr))

// ============================================================================
// Merged prep kernel (single launch), block-range dispatch:
//   [0, 8192)      : Pi + Pi2 fp32 -> fp16 into g_P16
//   [8192, 8704)   : x fp32 -> fp16
//   [8704, 12800)  : dequant pass 2 -> g_W16[:, NF:]
//   [12800, 13312) : zero the fp32 output (atomicAdd target of GEMM2)
// ============================================================================
#define PREP_BLOCKS 13312

__global__ void tq_prep_all(const float4* __restrict__ Pi, const float4* __restrict__ Pi2,
                            __half2* __restrict__ P16,
                            const float4* __restrict__ x, __half2* __restrict__ x16,
                            const int4* __restrict__ IP4, const float* __restrict__ NRM,
                            const float* __restrict__ CB, __half* __restrict__ W16,
                            float4* __restrict__ zo)
{
    const int b = blockIdx.x;

    if (b < 8192) {                       // --- P conversion (192 MB traffic)
        const int n4 = NF * NF / 4;
        int i = b * 1024 + threadIdx.x;
        #pragma unroll
        for (int j = 0; j < 4; ++j) {
            int k = i + j * 256;
            float4 v = (k < n4) ? Pi[k] : Pi2[k - n4];
            P16[2 * k]     = __floats2half2_rn(v.x, v.y);
            P16[2 * k + 1] = __floats2half2_rn(v.z, v.w);
        }
    } else if (b < 8704) {                // --- x conversion (10 MB)
        int i = (b - 8192) * 1024 + threadIdx.x;
        #pragma unroll
        for (int j = 0; j < 4; ++j) {
            int k = i + j * 256;
            float4 v = x[k];
            x16[2 * k]     = __floats2half2_rn(v.x, v.y);
            x16[2 * k + 1] = __floats2half2_rn(v.z, v.w);
        }
    } else if (b < 12800) {               // --- dequant pass 2 (64 MB)
        __shared__ float cb[16];
        if (threadIdx.x < 16) cb[threadIdx.x] = CB[threadIdx.x];
        __syncthreads();
        int base = (b - 8704) * 512 + threadIdx.x;
        #pragma unroll
        for (int u = 0; u < 2; ++u) {
            int i = base + u * 256;
            int m  = i >> 9;
            int c4 = i & 511;
            int4 p = IP4[i];
            float s = __ldg(&NRM[(m << 5) + (c4 >> 4)]) * 0.08838834764831843f;
            __half2 h[4];
            h[0] = __floats2half2_rn(cb[p.x & 15] * s, cb[(p.x >> 4) & 15] * s);
            h[1] = __floats2half2_rn(cb[p.y & 15] * s, cb[(p.y >> 4) & 15] * s);
            h[2] = __floats2half2_rn(cb[p.z & 15] * s, cb[(p.z >> 4) & 15] * s);
            h[3] = __floats2half2_rn(cb[p.w & 15] * s, cb[(p.w >> 4) & 15] * s);
            *reinterpret_cast<uint4*>(W16 + (size_t)m * (2 * NF) + NF + c4 * 8) =
                *reinterpret_cast<uint4*>(h);
        }
    } else {                              // --- zero out (8 MB)
        int i = (b - 12800) * 1024 + threadIdx.x;
        #pragma unroll
        for (int j = 0; j < 4; ++j)
            zo[i + j * 256] = make_float4(0.f, 0.f, 0.f, 0.f);
    }
}

// ============================================================================
// GEMM1 + aux: tile 128x128, 8 warps, warp 64x32, 3-stage cp.async,
//   fragment double-buffered (r10/r12 exact GEMM path).
//   Aux CTAs (blockIdx.y >= jTiles): dequant pass 1 only (64 MB, MLP 4).
// ============================================================================
__global__ void __launch_bounds__(256, 2)
tq_hgemm_aux(const __half* __restrict__ X, int ldx,
             const __half* __restrict__ W, int ldw,
             int ksteps, int jTiles, __half* __restrict__ Ch, int ldc,
             const int4* __restrict__ dq_i1, const float* __restrict__ dq_n1,
             const float* __restrict__ dq_c1, __half* __restrict__ dq_out)
{
    extern __shared__ __align__(1024) char dsm[];

    // ---------------- aux path: dq1 (64 MB over 40 CTAs) --------------------
    if ((int)blockIdx.y >= jTiles) {
        float* cb = reinterpret_cast<float*>(dsm);   // 16 floats
        if (threadIdx.x < 16) cb[threadIdx.x] = dq_c1[threadIdx.x];
        __syncthreads();
        const int auxId  = (blockIdx.y - jTiles) * gridDim.x + blockIdx.x;
        const int nAux   = AUX_Y * gridDim.x;        // 40
        const int total   = NF * (NF / 2) / 4;
        const int start4  = (auxId * 256 + threadIdx.x) * 4;
        const int stride4 = nAux * 256 * 4;
        for (int i0 = start4; i0 < total; i0 += stride4) {
            int4 p[4];
            #pragma unroll
            for (int u = 0; u < 4; ++u) p[u] = dq_i1[i0 + u];
            #pragma unroll
            for (int u = 0; u < 4; ++u) {
                int i  = i0 + u;
                int m  = i >> 9;
                int c4 = i & 511;
                float s = __ldg(&dq_n1[(m << 5) + (c4 >> 4)]) * 0.08838834764831843f;
                __half2 h[4];
                h[0] = __floats2half2_rn(cb[p[u].x & 15] * s, cb[(p[u].x >> 4) & 15] * s);
                h[1] = __floats2half2_rn(cb[p[u].y & 15] * s, cb[(p[u].y >> 4) & 15] * s);
                h[2] = __floats2half2_rn(cb[p[u].z & 15] * s, cb[(p[u].z >> 4) & 15] * s);
                h[3] = __floats2half2_rn(cb[p[u].w & 15] * s, cb[(p[u].w >> 4) & 15] * s);
                *reinterpret_cast<uint4*>(dq_out + (size_t)m * (2 * NF) + c4 * 8) =
                    *reinterpret_cast<uint4*>(h);
            }
        }
        return;
    }

    // ---------------- GEMM path (r12 exact) --------------------------------
    const uint32_t smBase = smem_u32(dsm);
    const int tid = threadIdx.x;
    const int wid = tid >> 5;
    const int lid = tid & 31;
    const int wm  = wid >> 2;
    const int wn  = wid & 3;
    const int tBase = blockIdx.x * TT;
    const int jBase = blockIdx.y * TJ;

    const __half* xb = X + (size_t)tBase * ldx;
    const __half* wb = W + (size_t)jBase * ldw;

    auto load_stage = [&](int slot, int step) {
        const int k0 = step * KSTEP;
        #pragma unroll
        for (int s = 0; s < 8; ++s) {
            int q = tid + s * 256;
            int r = q >> 3;
            int c = q & 7;
            const __half* src = (r < TT ? xb + (size_t)r * ldx
                                        : wb + (size_t)(r - TT) * ldw) + k0 + c * 8;
            uint32_t dst = smBase + slot * STAGE_BYTES + r * 128 + ((c ^ (r & 7)) * 16);
            asm volatile("cp.async.cg.shared.global [%0], [%1], 16;"
                         :: "r"(dst), "l"(src));
        }
    };

    const int swz  = lid & 7;
    const int rowA = wm * 64 + (lid & 7) + ((lid >> 3) & 1) * 8;
    const int pA   = lid >> 4;
    const int rowB = TT + wn * 32 + (lid & 7) + ((lid >> 4) & 1) * 8;
    const int pB   = (lid >> 3) & 1;

    float acc[4][4][4];
    #pragma unroll
    for (int a = 0; a < 4; ++a)
        #pragma unroll
        for (int b = 0; b < 4; ++b)
            #pragma unroll
            for (int c = 0; c < 4; ++c) acc[a][b][c] = 0.f;

    load_stage(0, 0);
    asm volatile("cp.async.commit_group;" ::: "memory");
    load_stage(1, 1);
    asm volatile("cp.async.commit_group;" ::: "memory");

    uint32_t a[2][4][4];
    uint32_t b[2][4][2];

    auto ldfrag = [&](int buf, uint32_t sb, int kb) {
        #pragma unroll
        for (int mi = 0; mi < 4; ++mi) {
            uint32_t ad = sb + (uint32_t)(rowA + mi * 16) * 128
                        + (uint32_t)(((kb * 2 + pA) ^ swz) * 16);
            TQ_LDSM4(a[buf][mi][0], a[buf][mi][1], a[buf][mi][2], a[buf][mi][3], ad);
        }
        #pragma unroll
        for (int gi = 0; gi < 2; ++gi) {
            uint32_t bd = sb + (uint32_t)(rowB + gi * 16) * 128
                        + (uint32_t)(((kb * 2 + pB) ^ swz) * 16);
            TQ_LDSM4(b[buf][2 * gi][0], b[buf][2 * gi][1],
                     b[buf][2 * gi + 1][0], b[buf][2 * gi + 1][1], bd);
        }
    };

    auto domma = [&](int buf) {
        #pragma unroll
        for (int mi = 0; mi < 4; ++mi)
            #pragma unroll
            for (int ni = 0; ni < 4; ++ni) {
                asm volatile(
                    "mma.sync.aligned.m16n8k16.row.col.f32.f16.f16.f32 "
                    "{%0,%1,%2,%3}, {%4,%5,%6,%7}, {%8,%9}, {%0,%1,%2,%3};"
                    : "+f"(acc[mi][ni][0]), "+f"(acc[mi][ni][1]),
                      "+f"(acc[mi][ni][2]), "+f"(acc[mi][ni][3])
                    : "r"(a[buf][mi][0]), "r"(a[buf][mi][1]),
                      "r"(a[buf][mi][2]), "r"(a[buf][mi][3]),
                      "r"(b[buf][ni][0]), "r"(b[buf][ni][1]));
            }
    };

    int slot = 0, pfslot = 2;
    for (int it = 0; it < ksteps; ++it) {
        asm volatile("cp.async.wait_group 1;" ::: "memory");
        __syncthreads();

        const int pf = it + NSTG - 1;
        if (pf < ksteps) load_stage(pfslot, pf);
        asm volatile("cp.async.commit_group;" ::: "memory");

        const uint32_t sb = smBase + slot * STAGE_BYTES;
        if (++slot == NSTG) slot = 0;
        if (++pfslot == NSTG) pfslot = 0;

        ldfrag(0, sb, 0);
        #pragma unroll
        for (int kb = 0; kb < 4; ++kb) {
            const int cur = kb & 1;
            if (kb < 3) ldfrag(cur ^ 1, sb, kb + 1);
            domma(cur);
        }
    }

    const int g  = lid >> 2;
    const int tg = lid & 3;
    #pragma unroll
    for (int mi = 0; mi < 4; ++mi) {
        #pragma unroll
        for (int ni = 0; ni < 4; ++ni) {
            int row = tBase + wm * 64 + mi * 16 + g;
            int col = jBase + wn * 32 + ni * 8 + tg * 2;
            __half2 h0 = __floats2half2_rn(acc[mi][ni][0], acc[mi][ni][1]);
            __half2 h1 = __floats2half2_rn(acc[mi][ni][2], acc[mi][ni][3]);
            *reinterpret_cast<__half2*>(Ch + (size_t)row * ldc + col)       = h0;
            *reinterpret_cast<__half2*>(Ch + (size_t)(row + 8) * ldc + col) = h1;
        }
    }
}

// ============================================================================
// GEMM2 (r12 exact): split-K 2, fp32 atomicAdd epilogue.
// ============================================================================
__global__ void __launch_bounds__(256, 2)
tq_hgemm2(const __half* __restrict__ X, int ldx,
          const __half* __restrict__ W, int ldw,
          int ksteps, float* __restrict__ Cf, int ldc)
{
    extern __shared__ __align__(1024) char dsm[];
    const uint32_t smBase = smem_u32(dsm);

    const int tid = threadIdx.x;
    const int wid = tid >> 5;
    const int lid = tid & 31;
    const int wm  = wid >> 2;
    const int wn  = wid & 3;
    const int tBase = blockIdx.x * TT;
    const int jBase = blockIdx.y * TJ;
    const int kOff  = blockIdx.z * (ksteps * KSTEP);

    const __half* xb = X + (size_t)tBase * ldx + kOff;
    const __half* wb = W + (size_t)jBase * ldw + kOff;

    auto load_stage = [&](int slot, int step) {
        const int k0 = step * KSTEP;
        #pragma unroll
        for (int s = 0; s < 8; ++s) {
            int q = tid + s * 256;
            int r = q >> 3;
            int c = q & 7;
            const __half* src = (r < TT ? xb + (size_t)r * ldx
                                        : wb + (size_t)(r - TT) * ldw) + k0 + c * 8;
            uint32_t dst = smBase + slot * STAGE_BYTES + r * 128 + ((c ^ (r & 7)) * 16);
            asm volatile("cp.async.cg.shared.global [%0], [%1], 16;"
                         :: "r"(dst), "l"(src));
        }
    };

    const int swz  = lid & 7;
    const int rowA = wm * 64 + (lid & 7) + ((lid >> 3) & 1) * 8;
    const int pA   = lid >> 4;
    const int rowB = TT + wn * 32 + (lid & 7) + ((lid >> 4) & 1) * 8;
    const int pB   = (lid >> 3) & 1;

    float acc[4][4][4];
    #pragma unroll
    for (int a = 0; a < 4; ++a)
        #pragma unroll
        for (int b = 0; b < 4; ++b)
            #pragma unroll
            for (int c = 0; c < 4; ++c) acc[a][b][c] = 0.f;

    load_stage(0, 0);
    asm volatile("cp.async.commit_group;" ::: "memory");
    load_stage(1, 1);
    asm volatile("cp.async.commit_group;" ::: "memory");

    uint32_t a[2][4][4];
    uint32_t b[2][4][2];

    auto ldfrag = [&](int buf, uint32_t sb, int kb) {
        #pragma unroll
        for (int mi = 0; mi < 4; ++mi) {
            uint32_t ad = sb + (uint32_t)(rowA + mi * 16) * 128
                        + (uint32_t)(((kb * 2 + pA) ^ swz) * 16);
            TQ_LDSM4(a[buf][mi][0], a[buf][mi][1], a[buf][mi][2], a[buf][mi][3], ad);
        }
        #pragma unroll
        for (int gi = 0; gi < 2; ++gi) {
            uint32_t bd = sb + (uint32_t)(rowB + gi * 16) * 128
                        + (uint32_t)(((kb * 2 + pB) ^ swz) * 16);
            TQ_LDSM4(b[buf][2 * gi][0], b[buf][2 * gi][1],
                     b[buf][2 * gi + 1][0], b[buf][2 * gi + 1][1], bd);
        }
    };

    auto domma = [&](int buf) {
        #pragma unroll
        for (int mi = 0; mi < 4; ++mi)
            #pragma unroll
            for (int ni = 0; ni < 4; ++ni) {
                asm volatile(
                    "mma.sync.aligned.m16n8k16.row.col.f32.f16.f16.f32 "
                    "{%0,%1,%2,%3}, {%4,%5,%6,%7}, {%8,%9}, {%0,%1,%2,%3};"
                    : "+f"(acc[mi][ni][0]), "+f"(acc[mi][ni][1]),
                      "+f"(acc[mi][ni][2]), "+f"(acc[mi][ni][3])
                    : "r"(a[buf][mi][0]), "r"(a[buf][mi][1]),
                      "r"(a[buf][mi][2]), "r"(a[buf][mi][3]),
                      "r"(b[buf][ni][0]), "r"(b[buf][ni][1]));
            }
    };

    int slot = 0, pfslot = 2;
    for (int it = 0; it < ksteps; ++it) {
        asm volatile("cp.async.wait_group 1;" ::: "memory");
        __syncthreads();

        const int pf = it + NSTG - 1;
        if (pf < ksteps) load_stage(pfslot, pf);
        asm volatile("cp.async.commit_group;" ::: "memory");

        const uint32_t sb = smBase + slot * STAGE_BYTES;
        if (++slot == NSTG) slot = 0;
        if (++pfslot == NSTG) pfslot = 0;

        ldfrag(0, sb, 0);
        #pragma unroll
        for (int kb = 0; kb < 4; ++kb) {
            const int cur = kb & 1;
            if (kb < 3) ldfrag(cur ^ 1, sb, kb + 1);
            domma(cur);
        }
    }

    const int g  = lid >> 2;
    const int tg = lid & 3;
    #pragma unroll
    for (int mi = 0; mi < 4; ++mi) {
        #pragma unroll
        for (int ni = 0; ni < 4; ++ni) {
            int row = tBase + wm * 64 + mi * 16 + g;
            int col = jBase + wn * 32 + ni * 8 + tg * 2;
            atomicAdd(Cf + (size_t)row * ldc + col,           acc[mi][ni][0]);
            atomicAdd(Cf + (size_t)row * ldc + col + 1,       acc[mi][ni][1]);
            atomicAdd(Cf + (size_t)(row + 8) * ldc + col,     acc[mi][ni][2]);
            atomicAdd(Cf + (size_t)(row + 8) * ldc + col + 1, acc[mi][ni][3]);
        }
    }
}

// ============================================================================
// Launch: prep_all, GEMM1+aux, GEMM2  (3 launches)
// ============================================================================
extern "C" void kernel_launch(void* const* d_in, const int* in_sizes, int n_in,
                              void* d_out, int out_size) {
    (void)in_sizes; (void)n_in; (void)out_size;
    const float* x    = (const float*)d_in[0];
    const float* Pi   = (const float*)d_in[1];
    const int*   idx1 = (const int*)  d_in[2];
    const float* nrm1 = (const float*)d_in[3];
    const float* cb1  = (const float*)d_in[4];
    const int*   idx2 = (const int*)  d_in[5];
    const float* nrm2 = (const float*)d_in[6];
    const float* cb2  = (const float*)d_in[7];
    const float* Pi2  = (const float*)d_in[8];
    float* out = (float*)d_out;

    __half *px16, *pP16, *pW16, *pxr;
    cudaGetSymbolAddress((void**)&px16, g_x16);
    cudaGetSymbolAddress((void**)&pP16, g_P16);
    cudaGetSymbolAddress((void**)&pW16, g_W16);
    cudaGetSymbolAddress((void**)&pxr,  g_xr);

    cudaFuncSetAttribute(tq_hgemm_aux, cudaFuncAttributeMaxDynamicSharedMemorySize,
                         SMEM_BYTES);
    cudaFuncSetAttribute(tq_hgemm2,    cudaFuncAttributeMaxDynamicSharedMemorySize,
                         SMEM_BYTES);

    // launch 1: all prep (P f2h, x f2h, dq2, zero out) in one launch
    tq_prep_all<<<PREP_BLOCKS, 256>>>(
        (const float4*)Pi, (const float4*)Pi2, (__half2*)pP16,
        (const float4*)x, (__half2*)px16,
        (const int4*)idx2, nrm2, cb2, pW16,
        (float4*)out);

    // launch 2: GEMM1 (256 CTAs) + 40 aux CTAs (dq1)
    //   xr[512, 8192] = x16 @ Pcat^T  (K = 4096)
    {
        dim3 grid(TOK / TT, 2 * NF / TJ + AUX_Y, 1);   // (4, 74) = 296 CTAs
        tq_hgemm_aux<<<grid, 256, SMEM_BYTES>>>(
            px16, NF, pP16, NF, NF / KSTEP, 2 * NF / TJ, pxr, 2 * NF,
            (const int4*)idx1, nrm1, cb1, pW16);
    }

    // launch 3: GEMM2  out += xr @ Wcat^T  (K = 8192, split-K 2)
    {
        dim3 grid(TOK / TT, NF / TJ, 2);               // (4, 32, 2) = 256 CTAs
        tq_hgemm2<<<grid, 256, SMEM_BYTES>>>(pxr, 2 * NF, pW16, 2 * NF,
                                             (2 * NF / KSTEP) / 2, out, NF);
    }
}